// round 8
// baseline (speedup 1.0000x reference)
#include <cuda_runtime.h>
#include <cuda_bf16.h>

// CT parallel-beam forward projection.
// vol: [1, 32, 256, 256] f32   phis: [180] f32 (degrees)
// out: [1, 180, 32, 256] f32
//
// Strategy:
//   Pass 1: transpose + zero-pad volume to volT[PY][PX][32] (z innermost).
//           One (y,x) voxel column = 32 floats = exactly one 128B line.
//   Pass 2: one warp per (angle, col). lane = neighbor(2b) * 8 + zquarter(3b).
//           Per t-sample: ONE dense LDG.128 fetches all 4 bilinear neighbors
//           x all 32 z; 4 FFMA per lane accumulate. Zero border + coordinate
//           clamp to [-1,256] exactly reproduces the reference's
//           zero-weight-for-invalid-neighbor semantics.

#define NZ     32
#define NXY    256
#define PAD    2
#define PDIM   (NXY + 2*PAD)     // 260
#define N_T    384
#define N_ANG  180

// padded transposed volume: [PDIM][PDIM][NZ] floats = 8.65 MB
__device__ __align__(128) float g_volT[PDIM * PDIM * NZ];

// ---------------------------------------------------------------------------
// Pass 1: fill volT (zero border + transposed interior). Deterministic, runs
// every launch.
// ---------------------------------------------------------------------------
__global__ void fill_volT_kernel(const float* __restrict__ vol) {
    int idx = blockIdx.x * blockDim.x + threadIdx.x;
    const int total = PDIM * PDIM * NZ;
    if (idx >= total) return;
    int z   = idx & (NZ - 1);
    int pxy = idx >> 5;               // NZ = 32
    int px  = pxy % PDIM;
    int py  = pxy / PDIM;
    int x = px - PAD;
    int y = py - PAD;
    float v = 0.0f;
    if ((unsigned)x < (unsigned)NXY && (unsigned)y < (unsigned)NXY) {
        // vol[z][y][x], strides 65536 / 256 / 1
        v = vol[(z << 16) + (y << 8) + x];
    }
    g_volT[idx] = v;
}

// ---------------------------------------------------------------------------
// Pass 2: projection. One warp per (angle, col).
//   blockDim = 256 (8 warps = 8 cols), gridDim.x = 180 * 32
// ---------------------------------------------------------------------------
__global__ void __launch_bounds__(256)
project_kernel(const float* __restrict__ phis, float* __restrict__ out) {
    const int a    = blockIdx.x >> 5;                               // angle
    const int j    = ((blockIdx.x & 31) << 3) + (threadIdx.x >> 5); // detector col
    const int lane = threadIdx.x & 31;

    const float phi = phis[a];
    const float ang = phi * 0.017453292519943295f;   // deg -> rad
    const float c = cosf(ang);
    const float s = sinf(ang);

    const float u   = (float)j - 127.5f;             // (nCols-1)/2 = 127.5
    // ix = c*t - s*u + 127.5 ; iy = s*t + c*u + 127.5
    const float bx0 = fmaf(-s, u, 127.5f);
    const float by0 = fmaf( c, u, 127.5f);

    // lane decomposition: nb = which bilinear neighbor, zq = z quarter
    const int nb  = lane >> 3;        // 0..3
    const int zq  = lane & 7;         // 0..7  -> z = 4*zq .. 4*zq+3
    const int dnx = nb & 1;
    const int dny = nb >> 1;

    // branch-free per-lane weight: w = (dnx? fx : 1-fx) * (dny? fy : 1-fy)
    const float sgx = dnx ? 1.0f : -1.0f;
    const float ofx = dnx ? 0.0f :  1.0f;
    const float sgy = dny ? 1.0f : -1.0f;
    const float ofy = dny ? 0.0f :  1.0f;

    // per-lane base pointer offset (floats): neighbor + z-quarter
    const float* __restrict__ basep =
        g_volT + ((dny * PDIM + dnx) * NZ + zq * 4);

    float4 acc = make_float4(0.f, 0.f, 0.f, 0.f);
    float tk = -(float)(N_T - 1) * 0.5f;   // -191.5, +1.0 per step (exact in fp32)

    #pragma unroll 4
    for (int k = 0; k < N_T; ++k, tk += 1.0f) {
        float ix = fmaf(c, tk, bx0);
        float iy = fmaf(s, tk, by0);
        // clamp into the zero-padded region: any fully-outside sample reads
        // pad zeros -> contribution 0, matching the reference masking exactly
        ix = fminf(fmaxf(ix, -1.0f), 256.0f);
        iy = fminf(fmaxf(iy, -1.0f), 256.0f);

        float fxf = floorf(ix);
        float fyf = floorf(iy);
        int   ix0 = (int)fxf;
        int   iy0 = (int)fyf;
        float fx  = ix - fxf;
        float fy  = iy - fyf;

        float w = fmaf(sgx, fx, ofx) * fmaf(sgy, fy, ofy);

        int idx = (iy0 + PAD) * PDIM + (ix0 + PAD);   // voxel-column index
        const float4 v = *reinterpret_cast<const float4*>(basep + idx * NZ);

        acc.x = fmaf(w, v.x, acc.x);
        acc.y = fmaf(w, v.y, acc.y);
        acc.z = fmaf(w, v.z, acc.z);
        acc.w = fmaf(w, v.w, acc.w);
    }

    // reduce the 4 neighbor partials (lanes differ in bits 3,4)
    acc.x += __shfl_xor_sync(0xFFFFFFFFu, acc.x, 8);
    acc.y += __shfl_xor_sync(0xFFFFFFFFu, acc.y, 8);
    acc.z += __shfl_xor_sync(0xFFFFFFFFu, acc.z, 8);
    acc.w += __shfl_xor_sync(0xFFFFFFFFu, acc.w, 8);
    acc.x += __shfl_xor_sync(0xFFFFFFFFu, acc.x, 16);
    acc.y += __shfl_xor_sync(0xFFFFFFFFu, acc.y, 16);
    acc.z += __shfl_xor_sync(0xFFFFFFFFu, acc.z, 16);
    acc.w += __shfl_xor_sync(0xFFFFFFFFu, acc.w, 16);

    if (nb == 0) {
        // out[a][z][j], z = 4*zq + {0,1,2,3}; z-stride = 256 floats
        int base = (a * NZ + zq * 4) * NXY + j;
        out[base          ] = acc.x;
        out[base + NXY    ] = acc.y;
        out[base + 2 * NXY] = acc.z;
        out[base + 3 * NXY] = acc.w;
    }
}

// ---------------------------------------------------------------------------
extern "C" void kernel_launch(void* const* d_in, const int* in_sizes, int n_in,
                              void* d_out, int out_size) {
    const float* vol  = (const float*)d_in[0];   // [1,32,256,256]
    const float* phis = (const float*)d_in[1];   // [180]
    float* out = (float*)d_out;                  // [1,180,32,256]

    (void)in_sizes; (void)n_in; (void)out_size;

    const int totalT = PDIM * PDIM * NZ;
    fill_volT_kernel<<<(totalT + 255) / 256, 256>>>(vol);

    // 180 angles * 32 blocks, 8 warps (= 8 cols) per block
    project_kernel<<<N_ANG * 32, 256>>>(phis, out);
}

// round 9
// speedup vs baseline: 1.5664x; 1.5664x over previous
#include <cuda_runtime.h>
#include <cuda_bf16.h>

// CT parallel-beam forward projection.
// vol: [1, 32, 256, 256] f32   phis: [180] f32 (degrees)
// out: [1, 180, 32, 256] f32
//
// Pass 1: transpose + zero-pad volume to volT[260][260][32] (z innermost).
//         One (y,x) voxel column = 32 floats = one 128B line.
// Pass 2: one warp per (angle, col). lane = neighbor(2b)*8 + zquarter(3b).
//         Per t-sample ONE dense warp LDG.128 covers all 4 bilinear
//         neighbors x 32 z. Per-ray t-range trimming skips the ~33% of
//         samples that lie outside the volume (their contribution is
//         exactly zero by the reference's validity masking), which also
//         makes coordinate clamps unnecessary.

#define NZ     32
#define NXY    256
#define PAD    2
#define PDIM   (NXY + 2*PAD)     // 260
#define N_T    384
#define N_ANG  180

// padded transposed volume: [PDIM][PDIM][NZ] floats = 8.65 MB
__device__ __align__(128) float g_volT[PDIM * PDIM * NZ];

// ---------------------------------------------------------------------------
// Pass 1: fill volT (zero border + transposed interior).
// ---------------------------------------------------------------------------
__global__ void fill_volT_kernel(const float* __restrict__ vol) {
    int idx = blockIdx.x * blockDim.x + threadIdx.x;
    const int total = PDIM * PDIM * NZ;
    if (idx >= total) return;
    int z   = idx & (NZ - 1);
    int pxy = idx >> 5;
    int px  = pxy % PDIM;
    int py  = pxy / PDIM;
    int x = px - PAD;
    int y = py - PAD;
    float v = 0.0f;
    if ((unsigned)x < (unsigned)NXY && (unsigned)y < (unsigned)NXY) {
        v = vol[(z << 16) + (y << 8) + x];   // vol[z][y][x]
    }
    g_volT[idx] = v;
}

// ---------------------------------------------------------------------------
// Pass 2: projection. One warp per (angle, col).
//   blockDim = 256 (8 warps = 8 cols), grid = 180 * 32
// ---------------------------------------------------------------------------
__global__ void __launch_bounds__(256)
project_kernel(const float* __restrict__ phis, float* __restrict__ out) {
    const int a    = blockIdx.x >> 5;                               // angle
    const int j    = ((blockIdx.x & 31) << 3) + (threadIdx.x >> 5); // detector col
    const int lane = threadIdx.x & 31;

    const float ang = phis[a] * 0.017453292519943295f;   // deg -> rad
    const float c = cosf(ang);
    const float s = sinf(ang);

    const float u   = (float)j - 127.5f;
    // ix = c*t - s*u + 127.5 ; iy = s*t + c*u + 127.5
    const float bx0 = fmaf(-s, u, 127.5f);
    const float by0 = fmaf( c, u, 127.5f);

    // ---- per-ray valid t-range: ix in (-1,256) AND iy in (-1,256) ----
    // (samples outside contribute exactly zero; boundary-exact samples have
    //  zero weight, so excluding them is also exact). s==0 only at phi=0
    //  with nonzero numerators -> +-inf, never NaN; min/max handle inf.
    const float ta = (-1.0f  - bx0) / c;
    const float tb = (256.0f - bx0) / c;
    const float tc = (-1.0f  - by0) / s;
    const float td = (256.0f - by0) / s;
    const float tlo = fmaxf(fmaxf(fminf(ta, tb), fminf(tc, td)), -191.5f);
    const float thi = fminf(fminf(fmaxf(ta, tb), fmaxf(tc, td)),  191.5f);
    const int klo = (int)ceilf (tlo + 191.5f);   // uniform across warp
    const int khi = (int)floorf(thi + 191.5f);

    // lane decomposition: nb = bilinear neighbor, zq = z quarter
    const int nb  = lane >> 3;        // 0..3
    const int zq  = lane & 7;         // 0..7  -> z = 4*zq .. 4*zq+3
    const int dnx = nb & 1;
    const int dny = nb >> 1;

    // branch-free per-lane weight: w = (dnx? fx : 1-fx) * (dny? fy : 1-fy)
    const float sgx = dnx ? 1.0f : -1.0f;
    const float ofx = dnx ? 0.0f :  1.0f;
    const float sgy = dny ? 1.0f : -1.0f;
    const float ofy = dny ? 0.0f :  1.0f;

    // per-lane base pointer: PAD offset folded in (idx may be negative,
    // min ix0/iy0 inside the trimmed range is -2, covered by PAD=2)
    const float* __restrict__ basep =
        g_volT + ((PAD * PDIM + PAD) * NZ) + ((dny * PDIM + dnx) * NZ + zq * 4);

    float4 acc = make_float4(0.f, 0.f, 0.f, 0.f);
    float tk = (float)klo - 191.5f;   // exact; +1.0 per step (exact in fp32)

    #pragma unroll 4
    for (int k = klo; k <= khi; ++k, tk += 1.0f) {
        const float ix = fmaf(c, tk, bx0);
        const float iy = fmaf(s, tk, by0);

        const float fxf = floorf(ix);
        const float fyf = floorf(iy);
        const float fx  = ix - fxf;
        const float fy  = iy - fyf;

        const float w = fmaf(sgx, fx, ofx) * fmaf(sgy, fy, ofy);

        // flat column index computed in float (exact: |idxf| < 2^17)
        const float idxf = fmaf(fyf, (float)PDIM, fxf);
        const int   idx  = (int)idxf;

        const float4 v = *reinterpret_cast<const float4*>(basep + idx * NZ);

        acc.x = fmaf(w, v.x, acc.x);
        acc.y = fmaf(w, v.y, acc.y);
        acc.z = fmaf(w, v.z, acc.z);
        acc.w = fmaf(w, v.w, acc.w);
    }

    // reduce the 4 neighbor partials (lanes differ in bits 3,4)
    acc.x += __shfl_xor_sync(0xFFFFFFFFu, acc.x, 8);
    acc.y += __shfl_xor_sync(0xFFFFFFFFu, acc.y, 8);
    acc.z += __shfl_xor_sync(0xFFFFFFFFu, acc.z, 8);
    acc.w += __shfl_xor_sync(0xFFFFFFFFu, acc.w, 8);
    acc.x += __shfl_xor_sync(0xFFFFFFFFu, acc.x, 16);
    acc.y += __shfl_xor_sync(0xFFFFFFFFu, acc.y, 16);
    acc.z += __shfl_xor_sync(0xFFFFFFFFu, acc.z, 16);
    acc.w += __shfl_xor_sync(0xFFFFFFFFu, acc.w, 16);

    if (nb == 0) {
        // out[a][z][j], z = 4*zq + {0,1,2,3}
        int base = (a * NZ + zq * 4) * NXY + j;
        out[base          ] = acc.x;
        out[base + NXY    ] = acc.y;
        out[base + 2 * NXY] = acc.z;
        out[base + 3 * NXY] = acc.w;
    }
}

// ---------------------------------------------------------------------------
extern "C" void kernel_launch(void* const* d_in, const int* in_sizes, int n_in,
                              void* d_out, int out_size) {
    const float* vol  = (const float*)d_in[0];   // [1,32,256,256]
    const float* phis = (const float*)d_in[1];   // [180]
    float* out = (float*)d_out;                  // [1,180,32,256]

    (void)in_sizes; (void)n_in; (void)out_size;

    const int totalT = PDIM * PDIM * NZ;
    fill_volT_kernel<<<(totalT + 255) / 256, 256>>>(vol);

    project_kernel<<<N_ANG * 32, 256>>>(phis, out);
}

// round 10
// speedup vs baseline: 1.7707x; 1.1304x over previous
#include <cuda_runtime.h>
#include <cuda_bf16.h>

// CT parallel-beam forward projection.
// vol: [1, 32, 256, 256] f32   phis: [180] f32 (degrees)
// out: [1, 180, 32, 256] f32
//
// Pass 1: transpose + zero-pad volume to volT[261][261][32] (z innermost,
//         2 pad cols low / 3 high). One (y,x) voxel column = one 128B line.
// Pass 2: one warp per (angle, col). lane = tpair(1b) | xneighbor(1b) | zq(3b):
//         each HALF-WARP processes a different t-sample (k and k+1), so all
//         index math is SIMD over two samples. Lanes cover the 2 x-neighbors;
//         the 2 y-neighbors come from a second LDG.128 at an immediate +1-row
//         offset, y-lerp folded into the weights. Per t-sample cost: ~11.5
//         warp-instructions and the irreducible 4 L1 wavefronts.
//         Per-ray t-range trimming skips samples outside the volume (their
//         contribution is exactly zero under the reference's masking).

#define NZ      32
#define NXY     256
#define PAD_LO  2
#define PAD_HI  3
#define PDIM    (NXY + PAD_LO + PAD_HI)   // 261
#define N_T     384
#define N_ANG   180

// padded transposed volume: [PDIM][PDIM][NZ] floats = 8.72 MB
__device__ __align__(128) float g_volT[PDIM * PDIM * NZ];

// ---------------------------------------------------------------------------
// Pass 1: fill volT (zero border + transposed interior).
// ---------------------------------------------------------------------------
__global__ void fill_volT_kernel(const float* __restrict__ vol) {
    int idx = blockIdx.x * blockDim.x + threadIdx.x;
    const int total = PDIM * PDIM * NZ;
    if (idx >= total) return;
    int z   = idx & (NZ - 1);
    int pxy = idx >> 5;
    int px  = pxy % PDIM;
    int py  = pxy / PDIM;
    int x = px - PAD_LO;
    int y = py - PAD_LO;
    float v = 0.0f;
    if ((unsigned)x < (unsigned)NXY && (unsigned)y < (unsigned)NXY) {
        v = vol[(z << 16) + (y << 8) + x];   // vol[z][y][x]
    }
    g_volT[idx] = v;
}

// ---------------------------------------------------------------------------
// Pass 2: projection. One warp per (angle, col).
//   blockDim = 256 (8 warps = 8 cols), grid = 180 * 32
// ---------------------------------------------------------------------------
__global__ void __launch_bounds__(256)
project_kernel(const float* __restrict__ phis, float* __restrict__ out) {
    const int a    = blockIdx.x >> 5;                               // angle
    const int j    = ((blockIdx.x & 31) << 3) + (threadIdx.x >> 5); // detector col
    const int lane = threadIdx.x & 31;

    const float ang = phis[a] * 0.017453292519943295f;   // deg -> rad
    const float c = cosf(ang);
    const float s = sinf(ang);

    const float u   = (float)j - 127.5f;
    // ix = c*t - s*u + 127.5 ; iy = s*t + c*u + 127.5
    const float bx0 = fmaf(-s, u, 127.5f);
    const float by0 = fmaf( c, u, 127.5f);

    // ---- per-ray valid t-range: ix in (-1,256) AND iy in (-1,256) ----
    // (outside samples contribute exactly zero; boundary-exact samples have
    //  zero weight). Division by 0 -> +-inf, handled by min/max; never NaN.
    const float ta = (-1.0f  - bx0) / c;
    const float tb = (256.0f - bx0) / c;
    const float tc = (-1.0f  - by0) / s;
    const float td = (256.0f - by0) / s;
    const float tlo = fmaxf(fmaxf(fminf(ta, tb), fminf(tc, td)), -191.5f);
    const float thi = fminf(fminf(fmaxf(ta, tb), fmaxf(tc, td)),  191.5f);
    const int klo = (int)ceilf (tlo + 191.5f);   // warp-uniform
    const int khi = (int)floorf(thi + 191.5f);
    const int kcnt  = max(khi - klo + 1, 0);
    const int npair = kcnt >> 1;                 // full (k, k+1) pairs
    const int tail  = kcnt & 1;

    // lane decomposition
    const int h   = lane >> 4;        // 0/1: which t-sample of the pair
    const int dnx = (lane >> 3) & 1;  // x-neighbor
    const int zq  = lane & 7;         // z quarter -> z = 4*zq .. 4*zq+3

    // branch-free x-weight: wx = dnx ? fx : 1-fx
    const float sgx = dnx ? 1.0f : -1.0f;
    const float ofx = dnx ? 0.0f :  1.0f;
    const float hw  = h   ? 0.0f :  1.0f;   // tail mask for the h=1 sample

    // per-lane base pointer (PAD folded in; idx may be negative down to
    // -(PAD_LO*PDIM+PAD_LO), covered exactly)
    const float* __restrict__ basep =
        g_volT + ((PAD_LO * PDIM + PAD_LO) * NZ) + (dnx * NZ + zq * 4);

    float4 acc = make_float4(0.f, 0.f, 0.f, 0.f);
    // per-lane t: sample k = klo + 2*i + h  (exact fp32 arithmetic)
    float tkl = (float)(klo + h) - 191.5f;

    #pragma unroll 2
    for (int i = 0; i < npair; ++i, tkl += 2.0f) {
        const float ix = fmaf(c, tkl, bx0);
        const float iy = fmaf(s, tkl, by0);

        const float fxf = floorf(ix);
        const float fyf = floorf(iy);
        const float fx  = ix - fxf;
        const float fy  = iy - fyf;

        const float wx = fmaf(sgx, fx, ofx);
        const float w1 = wx * fy;        // wx * fy        (row y0+1)
        const float w0 = wx - w1;        // wx * (1 - fy)  (row y0)

        const float idxf = fmaf(fyf, (float)PDIM, fxf);  // exact: |.| < 2^17
        const int   idx  = (int)idxf;

        const float4* p = reinterpret_cast<const float4*>(basep + idx * NZ);
        const float4 v0 = p[0];
        const float4 v1 = p[PDIM * NZ / 4];   // +1 y-row, immediate offset

        acc.x = fmaf(w0, v0.x, acc.x);
        acc.y = fmaf(w0, v0.y, acc.y);
        acc.z = fmaf(w0, v0.z, acc.z);
        acc.w = fmaf(w0, v0.w, acc.w);
        acc.x = fmaf(w1, v1.x, acc.x);
        acc.y = fmaf(w1, v1.y, acc.y);
        acc.z = fmaf(w1, v1.z, acc.z);
        acc.w = fmaf(w1, v1.w, acc.w);
    }

    if (tail) {
        // one more sample pair: h=0 lane is k=khi (valid), h=1 lane is
        // khi+1 -> weight forced to 0 (its address stays in-bounds: one
        // step of geometric overshoot lands in the zero pad).
        const float ix = fmaf(c, tkl, bx0);
        const float iy = fmaf(s, tkl, by0);
        const float fxf = floorf(ix);
        const float fyf = floorf(iy);
        const float fx  = ix - fxf;
        const float fy  = iy - fyf;

        const float wx = fmaf(sgx, fx, ofx) * hw;
        const float w1 = wx * fy;
        const float w0 = wx - w1;

        const float idxf = fmaf(fyf, (float)PDIM, fxf);
        const int   idx  = (int)idxf;
        const float4* p = reinterpret_cast<const float4*>(basep + idx * NZ);
        const float4 v0 = p[0];
        const float4 v1 = p[PDIM * NZ / 4];

        acc.x = fmaf(w0, v0.x, acc.x);
        acc.y = fmaf(w0, v0.y, acc.y);
        acc.z = fmaf(w0, v0.z, acc.z);
        acc.w = fmaf(w0, v0.w, acc.w);
        acc.x = fmaf(w1, v1.x, acc.x);
        acc.y = fmaf(w1, v1.y, acc.y);
        acc.z = fmaf(w1, v1.z, acc.z);
        acc.w = fmaf(w1, v1.w, acc.w);
    }

    // reduce over x-neighbor (bit 3) and t-pair half (bit 4)
    acc.x += __shfl_xor_sync(0xFFFFFFFFu, acc.x, 8);
    acc.y += __shfl_xor_sync(0xFFFFFFFFu, acc.y, 8);
    acc.z += __shfl_xor_sync(0xFFFFFFFFu, acc.z, 8);
    acc.w += __shfl_xor_sync(0xFFFFFFFFu, acc.w, 8);
    acc.x += __shfl_xor_sync(0xFFFFFFFFu, acc.x, 16);
    acc.y += __shfl_xor_sync(0xFFFFFFFFu, acc.y, 16);
    acc.z += __shfl_xor_sync(0xFFFFFFFFu, acc.z, 16);
    acc.w += __shfl_xor_sync(0xFFFFFFFFu, acc.w, 16);

    if ((lane >> 3) == 0) {
        // out[a][z][j], z = 4*zq + {0,1,2,3}
        int base = (a * NZ + zq * 4) * NXY + j;
        out[base          ] = acc.x;
        out[base + NXY    ] = acc.y;
        out[base + 2 * NXY] = acc.z;
        out[base + 3 * NXY] = acc.w;
    }
}

// ---------------------------------------------------------------------------
extern "C" void kernel_launch(void* const* d_in, const int* in_sizes, int n_in,
                              void* d_out, int out_size) {
    const float* vol  = (const float*)d_in[0];   // [1,32,256,256]
    const float* phis = (const float*)d_in[1];   // [180]
    float* out = (float*)d_out;                  // [1,180,32,256]

    (void)in_sizes; (void)n_in; (void)out_size;

    const int totalT = PDIM * PDIM * NZ;
    fill_volT_kernel<<<(totalT + 255) / 256, 256>>>(vol);

    project_kernel<<<N_ANG * 32, 256>>>(phis, out);
}

// round 11
// speedup vs baseline: 1.7958x; 1.0142x over previous
#include <cuda_runtime.h>
#include <cuda_bf16.h>

// CT parallel-beam forward projection.
// vol: [1, 32, 256, 256] f32   phis: [180] f32 (degrees)
// out: [1, 180, 32, 256] f32
//
// Pass 1: transpose + zero-pad volume to volT[261][261][32] (z innermost).
// Pass 2: one warp per (angle, col). lane = tpair(1b)|xneighbor(1b)|zq(3b):
//         each half-warp handles a different t-sample; 2 x-neighbors across
//         lanes; 2 y-neighbors via a second LDG at +1 row with the y-lerp
//         folded into weights. Main loop processes TWO pairs (4 samples) per
//         iteration with all four LDG.128 front-batched (MLP=4) to hide
//         L1/L2 latency. Per-ray t-range trimming skips samples outside the
//         volume (exactly zero contribution under the reference's masking).

#define NZ      32
#define NXY     256
#define PAD_LO  2
#define PAD_HI  3
#define PDIM    (NXY + PAD_LO + PAD_HI)   // 261
#define N_T     384
#define N_ANG   180
#define ROWOFF  (PDIM * NZ / 4)           // +1 y-row in float4 units

// padded transposed volume: [PDIM][PDIM][NZ] floats = 8.72 MB
__device__ __align__(128) float g_volT[PDIM * PDIM * NZ];

// ---------------------------------------------------------------------------
// Pass 1: fill volT (zero border + transposed interior).
// ---------------------------------------------------------------------------
__global__ void fill_volT_kernel(const float* __restrict__ vol) {
    int idx = blockIdx.x * blockDim.x + threadIdx.x;
    const int total = PDIM * PDIM * NZ;
    if (idx >= total) return;
    int z   = idx & (NZ - 1);
    int pxy = idx >> 5;
    int px  = pxy % PDIM;
    int py  = pxy / PDIM;
    int x = px - PAD_LO;
    int y = py - PAD_LO;
    float v = 0.0f;
    if ((unsigned)x < (unsigned)NXY && (unsigned)y < (unsigned)NXY) {
        v = vol[(z << 16) + (y << 8) + x];   // vol[z][y][x]
    }
    g_volT[idx] = v;
}

// ---------------------------------------------------------------------------
// Pass 2: projection. One warp per (angle, col).
//   blockDim = 128 (4 warps = 4 cols), grid = 180 * 64
// ---------------------------------------------------------------------------
__global__ void __launch_bounds__(128)
project_kernel(const float* __restrict__ phis, float* __restrict__ out) {
    const int a    = blockIdx.x >> 6;                               // angle
    const int j    = ((blockIdx.x & 63) << 2) + (threadIdx.x >> 5); // detector col
    const int lane = threadIdx.x & 31;

    const float ang = phis[a] * 0.017453292519943295f;   // deg -> rad
    const float c = cosf(ang);
    const float s = sinf(ang);

    const float u   = (float)j - 127.5f;
    // ix = c*t - s*u + 127.5 ; iy = s*t + c*u + 127.5
    const float bx0 = fmaf(-s, u, 127.5f);
    const float by0 = fmaf( c, u, 127.5f);

    // ---- per-ray valid t-range: ix in (-1,256) AND iy in (-1,256) ----
    const float ta = (-1.0f  - bx0) / c;
    const float tb = (256.0f - bx0) / c;
    const float tc = (-1.0f  - by0) / s;
    const float td = (256.0f - by0) / s;
    const float tlo = fmaxf(fmaxf(fminf(ta, tb), fminf(tc, td)), -191.5f);
    const float thi = fminf(fminf(fmaxf(ta, tb), fmaxf(tc, td)),  191.5f);
    const int klo = (int)ceilf (tlo + 191.5f);   // warp-uniform
    const int khi = (int)floorf(thi + 191.5f);
    const int kcnt  = max(khi - klo + 1, 0);
    const int npair = kcnt >> 1;                 // full (k, k+1) pairs
    const int tail  = kcnt & 1;

    // lane decomposition
    const int h   = lane >> 4;        // 0/1: which t-sample of the pair
    const int dnx = (lane >> 3) & 1;  // x-neighbor
    const int zq  = lane & 7;         // z quarter -> z = 4*zq .. 4*zq+3

    // branch-free x-weight: wx = dnx ? fx : 1-fx
    const float sgx = dnx ? 1.0f : -1.0f;
    const float ofx = dnx ? 0.0f :  1.0f;
    const float hw  = h   ? 0.0f :  1.0f;   // tail mask for the h=1 sample

    const float* __restrict__ basep =
        g_volT + ((PAD_LO * PDIM + PAD_LO) * NZ) + (dnx * NZ + zq * 4);

    float4 acc = make_float4(0.f, 0.f, 0.f, 0.f);
    // per-lane t of pair i: klo + 2*i + h  (all values exact in fp32)
    float tkl = (float)(klo + h) - 191.5f;

    // ================= main loop: 2 pairs (4 samples) / iter ===============
    int i = 0;
    #pragma unroll 1
    for (; i + 2 <= npair; i += 2, tkl += 4.0f) {
        const float tka = tkl;
        const float tkb = tkl + 2.0f;          // exact

        // --- addresses for both pairs ---
        const float ixa = fmaf(c, tka, bx0);
        const float iya = fmaf(s, tka, by0);
        const float ixb = fmaf(c, tkb, bx0);
        const float iyb = fmaf(s, tkb, by0);

        const float fxfa = floorf(ixa), fyfa = floorf(iya);
        const float fxfb = floorf(ixb), fyfb = floorf(iyb);

        const int idxa = (int)fmaf(fyfa, (float)PDIM, fxfa);
        const int idxb = (int)fmaf(fyfb, (float)PDIM, fxfb);

        const float4* pa = reinterpret_cast<const float4*>(basep + idxa * NZ);
        const float4* pb = reinterpret_cast<const float4*>(basep + idxb * NZ);

        // --- front-batched loads (4 independent LDG.128) ---
        const float4 va0 = pa[0];
        const float4 va1 = pa[ROWOFF];
        const float4 vb0 = pb[0];
        const float4 vb1 = pb[ROWOFF];

        // --- weights ---
        const float fxa = ixa - fxfa, fya = iya - fyfa;
        const float fxb = ixb - fxfb, fyb = iyb - fyfb;

        const float wxa = fmaf(sgx, fxa, ofx);
        const float wa1 = wxa * fya;
        const float wa0 = wxa - wa1;
        const float wxb = fmaf(sgx, fxb, ofx);
        const float wb1 = wxb * fyb;
        const float wb0 = wxb - wb1;

        // --- 16 FMAs over 4 independent chains ---
        acc.x = fmaf(wa0, va0.x, acc.x);
        acc.y = fmaf(wa0, va0.y, acc.y);
        acc.z = fmaf(wa0, va0.z, acc.z);
        acc.w = fmaf(wa0, va0.w, acc.w);
        acc.x = fmaf(wa1, va1.x, acc.x);
        acc.y = fmaf(wa1, va1.y, acc.y);
        acc.z = fmaf(wa1, va1.z, acc.z);
        acc.w = fmaf(wa1, va1.w, acc.w);
        acc.x = fmaf(wb0, vb0.x, acc.x);
        acc.y = fmaf(wb0, vb0.y, acc.y);
        acc.z = fmaf(wb0, vb0.z, acc.z);
        acc.w = fmaf(wb0, vb0.w, acc.w);
        acc.x = fmaf(wb1, vb1.x, acc.x);
        acc.y = fmaf(wb1, vb1.y, acc.y);
        acc.z = fmaf(wb1, vb1.z, acc.z);
        acc.w = fmaf(wb1, vb1.w, acc.w);
    }

    // ================= remainder: one pair =================================
    if (i < npair) {
        const float ix = fmaf(c, tkl, bx0);
        const float iy = fmaf(s, tkl, by0);
        const float fxf = floorf(ix), fyf = floorf(iy);
        const float fx = ix - fxf,    fy = iy - fyf;

        const float wx = fmaf(sgx, fx, ofx);
        const float w1 = wx * fy;
        const float w0 = wx - w1;

        const int idx = (int)fmaf(fyf, (float)PDIM, fxf);
        const float4* p = reinterpret_cast<const float4*>(basep + idx * NZ);
        const float4 v0 = p[0];
        const float4 v1 = p[ROWOFF];

        acc.x = fmaf(w0, v0.x, acc.x);
        acc.y = fmaf(w0, v0.y, acc.y);
        acc.z = fmaf(w0, v0.z, acc.z);
        acc.w = fmaf(w0, v0.w, acc.w);
        acc.x = fmaf(w1, v1.x, acc.x);
        acc.y = fmaf(w1, v1.y, acc.y);
        acc.z = fmaf(w1, v1.z, acc.z);
        acc.w = fmaf(w1, v1.w, acc.w);
        tkl += 2.0f;
    }

    // ================= tail: odd sample count ==============================
    if (tail) {
        // h=0 lane is k=khi (valid), h=1 lane is khi+1 -> weight forced 0
        // (one step of geometric overshoot lands in the zero pad).
        const float ix = fmaf(c, tkl, bx0);
        const float iy = fmaf(s, tkl, by0);
        const float fxf = floorf(ix), fyf = floorf(iy);
        const float fx = ix - fxf,    fy = iy - fyf;

        const float wx = fmaf(sgx, fx, ofx) * hw;
        const float w1 = wx * fy;
        const float w0 = wx - w1;

        const int idx = (int)fmaf(fyf, (float)PDIM, fxf);
        const float4* p = reinterpret_cast<const float4*>(basep + idx * NZ);
        const float4 v0 = p[0];
        const float4 v1 = p[ROWOFF];

        acc.x = fmaf(w0, v0.x, acc.x);
        acc.y = fmaf(w0, v0.y, acc.y);
        acc.z = fmaf(w0, v0.z, acc.z);
        acc.w = fmaf(w0, v0.w, acc.w);
        acc.x = fmaf(w1, v1.x, acc.x);
        acc.y = fmaf(w1, v1.y, acc.y);
        acc.z = fmaf(w1, v1.z, acc.z);
        acc.w = fmaf(w1, v1.w, acc.w);
    }

    // reduce over x-neighbor (bit 3) and t-pair half (bit 4)
    acc.x += __shfl_xor_sync(0xFFFFFFFFu, acc.x, 8);
    acc.y += __shfl_xor_sync(0xFFFFFFFFu, acc.y, 8);
    acc.z += __shfl_xor_sync(0xFFFFFFFFu, acc.z, 8);
    acc.w += __shfl_xor_sync(0xFFFFFFFFu, acc.w, 8);
    acc.x += __shfl_xor_sync(0xFFFFFFFFu, acc.x, 16);
    acc.y += __shfl_xor_sync(0xFFFFFFFFu, acc.y, 16);
    acc.z += __shfl_xor_sync(0xFFFFFFFFu, acc.z, 16);
    acc.w += __shfl_xor_sync(0xFFFFFFFFu, acc.w, 16);

    if ((lane >> 3) == 0) {
        // out[a][z][j], z = 4*zq + {0,1,2,3}
        int base = (a * NZ + zq * 4) * NXY + j;
        out[base          ] = acc.x;
        out[base + NXY    ] = acc.y;
        out[base + 2 * NXY] = acc.z;
        out[base + 3 * NXY] = acc.w;
    }
}

// ---------------------------------------------------------------------------
extern "C" void kernel_launch(void* const* d_in, const int* in_sizes, int n_in,
                              void* d_out, int out_size) {
    const float* vol  = (const float*)d_in[0];   // [1,32,256,256]
    const float* phis = (const float*)d_in[1];   // [180]
    float* out = (float*)d_out;                  // [1,180,32,256]

    (void)in_sizes; (void)n_in; (void)out_size;

    const int totalT = PDIM * PDIM * NZ;
    fill_volT_kernel<<<(totalT + 255) / 256, 256>>>(vol);

    project_kernel<<<N_ANG * 64, 128>>>(phis, out);
}